// round 2
// baseline (speedup 1.0000x reference)
#include <cuda_runtime.h>

#define NANCH 19200      // 3*80*80 anchors per image
#define NIMG  8
#define MTGT  100
#define NCLS  80
#define THREADS 64
#define APT 4                               // anchors per thread
#define ANCH_PER_BLK (THREADS * APT)        // 256
#define NBLK_PER_IMG (NANCH / ANCH_PER_BLK) // 75
#define NBLOCKS (NIMG * NBLK_PER_IMG)       // 600

__device__ float    g_part[NBLOCKS * 4];
__device__ unsigned g_count;

__global__ void __launch_bounds__(THREADS) loss_fused(
    const float* __restrict__ obj,    // [8,19200]
    const float* __restrict__ boxes,  // [8,19200,4] (cx,cy,w,h)
    const float* __restrict__ cls,    // [8,19200,80]
    const float* __restrict__ tbox,   // [8,100,4]
    const int*   __restrict__ tlab,   // [8,100]
    float*       __restrict__ out)
{
    __shared__ float4 s_lohi[MTGT];          // lox,loy,hix,hiy
    __shared__ float  s_area[MTGT];
    __shared__ int    s_lab[MTGT];
    __shared__ int    s_pos_row[ANCH_PER_BLK];
    __shared__ int    s_pos_lab[ANCH_PER_BLK];
    __shared__ int    s_wtot[2];
    __shared__ float  s_red[2];
    __shared__ float  s_img[NIMG][4];
    __shared__ unsigned s_is_last;

    const int tid  = threadIdx.x;
    const int lane = tid & 31;
    const int wid  = tid >> 5;
    const int img  = blockIdx.x / NBLK_PER_IMG;
    const int ablk = blockIdx.x % NBLK_PER_IMG;
    const int base = img * NANCH + ablk * ANCH_PER_BLK + tid * APT;

    // ── Targets to shared ──
    if (tid < MTGT) {
        float4 tb = ((const float4*)tbox)[img * MTGT + tid];
        s_lohi[tid] = make_float4(tb.x - 0.5f * tb.z, tb.y - 0.5f * tb.w,
                                  tb.x + 0.5f * tb.z, tb.y + 0.5f * tb.w);
        s_area[tid] = tb.z * tb.w;
        s_lab[tid]  = tlab[img * MTGT + tid];
    } else if (tid >= 32 && tid - 32 < MTGT - 64) {
        // nothing; (MTGT=100 > 64 threads) handled below
    }
    // second pass for targets 64..99
    if (tid + THREADS < MTGT) {
        int m = tid + THREADS;
        float4 tb = ((const float4*)tbox)[img * MTGT + m];
        s_lohi[m] = make_float4(tb.x - 0.5f * tb.z, tb.y - 0.5f * tb.w,
                                tb.x + 0.5f * tb.z, tb.y + 0.5f * tb.w);
        s_area[m] = tb.z * tb.w;
        s_lab[m]  = tlab[img * MTGT + m];
    }
    __syncthreads();

    // ── Load 4 anchor boxes ──
    float lo1x[APT], lo1y[APT], hi1x[APT], hi1y[APT], a1[APT];
    float bi[APT], bu[APT];
    int   bidx[APT];
    #pragma unroll
    for (int a = 0; a < APT; a++) {
        float4 bx = ((const float4*)boxes)[base + a];
        lo1x[a] = bx.x - 0.5f * bx.z;  lo1y[a] = bx.y - 0.5f * bx.w;
        hi1x[a] = bx.x + 0.5f * bx.z;  hi1y[a] = bx.y + 0.5f * bx.w;
        a1[a]   = bx.z * bx.w + 1e-6f;
        bi[a] = -1.0f; bu[a] = 1.0f; bidx[a] = 0;
    }

    // ── IoU argmax over 100 targets, division-free, 4-way ILP ──
    #pragma unroll 4
    for (int m = 0; m < MTGT; m++) {
        float4 t  = s_lohi[m];
        float  ta = s_area[m];
        #pragma unroll
        for (int a = 0; a < APT; a++) {
            float wx = fmaxf(fminf(hi1x[a], t.z) - fmaxf(lo1x[a], t.x), 0.0f);
            float wy = fmaxf(fminf(hi1y[a], t.w) - fmaxf(lo1y[a], t.y), 0.0f);
            float inter = wx * wy;
            float u = a1[a] + ta - inter;   // union + 1e-6
            if (inter * bu[a] > bi[a] * u) { bi[a] = inter; bu[a] = u; bidx[a] = m; }
        }
    }

    // ── per-anchor: pos flag, BCE, GIoU ──
    bool  pos[APT];
    float bce = 0.0f, posf_sum = 0.0f, bbox = 0.0f;
    #pragma unroll
    for (int a = 0; a < APT; a++) {
        pos[a] = (bi[a] >= 0.5f * bu[a]);
        float o = obj[base + a];
        bce += pos[a] ? -fmaxf(__logf(o), -100.0f)
                      : -fmaxf(__logf(1.0f - o), -100.0f);
        if (pos[a]) {
            posf_sum += 1.0f;
            float4 t = s_lohi[bidx[a]];
            float wx = fmaxf(fminf(hi1x[a], t.z) - fmaxf(lo1x[a], t.x), 0.0f);
            float wy = fmaxf(fminf(hi1y[a], t.w) - fmaxf(lo1y[a], t.y), 0.0f);
            float inter = wx * wy;
            float uni = (a1[a] - 1e-6f) + s_area[bidx[a]] - inter;
            float iou = __fdividef(inter, uni + 1e-6f);
            float ex = fmaxf(fmaxf(hi1x[a], t.z) - fminf(lo1x[a], t.x), 0.0f);
            float ey = fmaxf(fmaxf(hi1y[a], t.w) - fminf(lo1y[a], t.y), 0.0f);
            float enc = ex * ey;
            bbox += 1.0f - (iou - __fdividef(enc - uni, enc + 1e-6f));
        }
    }

    // ── deterministic compaction of positives ──
    int c = 0;
    #pragma unroll
    for (int a = 0; a < APT; a++) c += pos[a] ? 1 : 0;
    int pre = c;
    #pragma unroll
    for (int o = 1; o < 32; o <<= 1) {
        int n = __shfl_up_sync(0xFFFFFFFFu, pre, o);
        if (lane >= o) pre += n;
    }
    if (lane == 31) s_wtot[wid] = pre;
    __syncthreads();
    int ofs = (wid == 1 ? s_wtot[0] : 0) + pre - c;  // exclusive prefix
    int P   = s_wtot[0] + s_wtot[1];
    #pragma unroll
    for (int a = 0; a < APT; a++) {
        if (pos[a]) {
            s_pos_row[ofs] = base + a;
            s_pos_lab[ofs] = s_lab[bidx[a]];
            ofs++;
        }
    }
    __syncthreads();

    // ── focal loss over positives (P*80 items, cooperative) ──
    float fl = 0.0f;
    const int items = P * NCLS;
    for (int i = tid; i < items; i += THREADS) {
        int a = i / NCLS;
        int ccol = i - a * NCLS;
        float x = cls[s_pos_row[a] * NCLS + ccol];
        bool t = (ccol == s_pos_lab[a]);
        float e  = __expf(-fabsf(x));
        float sp = __logf(1.0f + e);
        float s  = __fdividef(1.0f, 1.0f + e);
        float p  = (x >= 0.0f) ? s : (1.0f - s);
        float one_m_pt = t ? (1.0f - p) : p;
        float ce = sp + fmaxf(t ? -x : x, 0.0f);
        float at = t ? 0.25f : 0.75f;
        fl += at * one_m_pt * one_m_pt * ce;
    }

    // ── block reduction of (bce, posf, bbox, fl) — deterministic ──
    float vals[4] = {bce, posf_sum, bbox, fl};
    #pragma unroll
    for (int k = 0; k < 4; k++) {
        float v = vals[k];
        #pragma unroll
        for (int o = 16; o > 0; o >>= 1) v += __shfl_down_sync(0xFFFFFFFFu, v, o);
        if (lane == 0) s_red[wid] = v;
        __syncthreads();
        if (tid == 0) g_part[blockIdx.x * 4 + k] = s_red[0] + s_red[1];
        __syncthreads();
    }

    // ── last-block finalize ──
    __threadfence();
    if (tid == 0) s_is_last = (atomicAdd(&g_count, 1) == NBLOCKS - 1) ? 1u : 0u;
    __syncthreads();
    if (!s_is_last) return;
    __threadfence();

    {
        int fimg = tid >> 3;        // 0..7
        int sub  = tid & 7;         // 0..7
        float v0 = 0, v1 = 0, v2 = 0, v3 = 0;
        for (int s = sub; s < NBLK_PER_IMG; s += 8) {
            int b = fimg * NBLK_PER_IMG + s;
            v0 += g_part[b * 4 + 0];
            v1 += g_part[b * 4 + 1];
            v2 += g_part[b * 4 + 2];
            v3 += g_part[b * 4 + 3];
        }
        #pragma unroll
        for (int o = 4; o > 0; o >>= 1) {
            v0 += __shfl_down_sync(0xFFFFFFFFu, v0, o);
            v1 += __shfl_down_sync(0xFFFFFFFFu, v1, o);
            v2 += __shfl_down_sync(0xFFFFFFFFu, v2, o);
            v3 += __shfl_down_sync(0xFFFFFFFFu, v3, o);
        }
        if (sub == 0) {
            s_img[fimg][0] = v0; s_img[fimg][1] = v1;
            s_img[fimg][2] = v2; s_img[fimg][3] = v3;
        }
        __syncthreads();
        if (tid == 0) {
            float obj_sum = 0, bbox_sum = 0, cls_sum = 0, num_pos = 0;
            #pragma unroll
            for (int i = 0; i < NIMG; i++) {
                float bces = s_img[i][0];
                float pc   = s_img[i][1];
                float bb   = s_img[i][2];
                float fls  = s_img[i][3];
                obj_sum  += bces * (1.0f * pc + 0.5f * ((float)NANCH - pc));
                bbox_sum += bb;
                cls_sum  += fls / fmaxf(pc * (float)NCLS, 1.0f);
                num_pos  += pc;
            }
            num_pos = fmaxf(num_pos, 1.0f);
            out[0] = obj_sum / (float)NIMG
                   + 5.0f * bbox_sum / num_pos
                   + cls_sum / (float)NIMG;
            g_count = 0;   // reset for next graph replay
        }
    }
}

extern "C" void kernel_launch(void* const* d_in, const int* in_sizes, int n_in,
                              void* d_out, int out_size) {
    const float* obj   = (const float*)d_in[0];
    const float* boxes = (const float*)d_in[1];
    const float* cls   = (const float*)d_in[2];
    const float* tbox  = (const float*)d_in[3];
    const int*   tlab  = (const int*)d_in[4];
    float* out = (float*)d_out;

    loss_fused<<<NBLOCKS, THREADS>>>(obj, boxes, cls, tbox, tlab, out);
}

// round 3
// speedup vs baseline: 1.1515x; 1.1515x over previous
#include <cuda_runtime.h>

#define NANCH 19200      // 3*80*80 anchors per image
#define NIMG  8
#define MTGT  100
#define NCLS  80
#define THREADS 128
#define NWARP (THREADS / 32)
#define APT 2                               // anchors per thread
#define ANCH_PER_BLK (THREADS * APT)        // 256
#define NBLK_PER_IMG (NANCH / ANCH_PER_BLK) // 75
#define NBLOCKS (NIMG * NBLK_PER_IMG)       // 600

__device__ float    g_part[NBLOCKS * 4];
__device__ unsigned g_count;

__global__ void __launch_bounds__(THREADS) loss_fused(
    const float* __restrict__ obj,    // [8,19200]
    const float* __restrict__ boxes,  // [8,19200,4] (cx,cy,w,h)
    const float* __restrict__ cls,    // [8,19200,80]
    const float* __restrict__ tbox,   // [8,100,4]
    const int*   __restrict__ tlab,   // [8,100]
    float*       __restrict__ out)
{
    __shared__ float4 s_lohi[MTGT];          // lox,loy,hix,hiy
    __shared__ float  s_area[MTGT];
    __shared__ int    s_lab[MTGT];
    __shared__ int    s_pos_row[ANCH_PER_BLK];
    __shared__ int    s_pos_lab[ANCH_PER_BLK];
    __shared__ int    s_wtot[NWARP];
    __shared__ float  s_red[NWARP];
    __shared__ float  s_img[NIMG][4];
    __shared__ unsigned s_is_last;

    const int tid  = threadIdx.x;
    const int lane = tid & 31;
    const int wid  = tid >> 5;
    const int img  = blockIdx.x / NBLK_PER_IMG;
    const int ablk = blockIdx.x % NBLK_PER_IMG;
    const int base = img * NANCH + ablk * ANCH_PER_BLK + tid * APT;

    // ── Targets to shared (128 threads cover 100 targets in one pass) ──
    if (tid < MTGT) {
        float4 tb = ((const float4*)tbox)[img * MTGT + tid];
        s_lohi[tid] = make_float4(tb.x - 0.5f * tb.z, tb.y - 0.5f * tb.w,
                                  tb.x + 0.5f * tb.z, tb.y + 0.5f * tb.w);
        s_area[tid] = tb.z * tb.w;
        s_lab[tid]  = tlab[img * MTGT + tid];
    }
    __syncthreads();

    // ── Load anchor boxes ──
    float lo1x[APT], lo1y[APT], hi1x[APT], hi1y[APT], a1[APT];
    float bi0[APT], bu0[APT], bi1[APT], bu1[APT];
    int   bidx0[APT], bidx1[APT];
    #pragma unroll
    for (int a = 0; a < APT; a++) {
        float4 bx = ((const float4*)boxes)[base + a];
        lo1x[a] = bx.x - 0.5f * bx.z;  lo1y[a] = bx.y - 0.5f * bx.w;
        hi1x[a] = bx.x + 0.5f * bx.z;  hi1y[a] = bx.y + 0.5f * bx.w;
        a1[a]   = bx.z * bx.w + 1e-6f;
        bi0[a] = -1.0f; bu0[a] = 1.0f; bidx0[a] = 0;
        bi1[a] = -1.0f; bu1[a] = 1.0f; bidx1[a] = 0;
    }

    // ── IoU argmax: division-free, 2 anchors x 2 independent chains ──
    #pragma unroll 2
    for (int m = 0; m < MTGT; m += 2) {
        float4 t0  = s_lohi[m];     float ta0 = s_area[m];
        float4 t1  = s_lohi[m + 1]; float ta1 = s_area[m + 1];
        #pragma unroll
        for (int a = 0; a < APT; a++) {
            // chain 0 (even targets)
            float wx = fmaxf(fminf(hi1x[a], t0.z) - fmaxf(lo1x[a], t0.x), 0.0f);
            float wy = fmaxf(fminf(hi1y[a], t0.w) - fmaxf(lo1y[a], t0.y), 0.0f);
            float inter = wx * wy;
            float u = a1[a] + ta0 - inter;
            if (inter * bu0[a] > bi0[a] * u) { bi0[a] = inter; bu0[a] = u; bidx0[a] = m; }
            // chain 1 (odd targets)
            float wx1 = fmaxf(fminf(hi1x[a], t1.z) - fmaxf(lo1x[a], t1.x), 0.0f);
            float wy1 = fmaxf(fminf(hi1y[a], t1.w) - fmaxf(lo1y[a], t1.y), 0.0f);
            float inter1 = wx1 * wy1;
            float u1 = a1[a] + ta1 - inter1;
            if (inter1 * bu1[a] > bi1[a] * u1) { bi1[a] = inter1; bu1[a] = u1; bidx1[a] = m + 1; }
        }
    }

    // ── per-anchor: merge chains, pos flag, BCE, GIoU ──
    bool  pos[APT];
    int   bidx[APT];
    float bce = 0.0f, posf_sum = 0.0f, bbox = 0.0f;
    #pragma unroll
    for (int a = 0; a < APT; a++) {
        // merge (strict >: on exact tie keep even chain; ties are measure-zero)
        bool c1 = (bi1[a] * bu0[a] > bi0[a] * bu1[a]);
        float bi = c1 ? bi1[a] : bi0[a];
        float bu = c1 ? bu1[a] : bu0[a];
        bidx[a]  = c1 ? bidx1[a] : bidx0[a];
        pos[a] = (bi >= 0.5f * bu);
        float o = obj[base + a];
        bce += pos[a] ? -fmaxf(__logf(o), -100.0f)
                      : -fmaxf(__logf(1.0f - o), -100.0f);
        if (pos[a]) {
            posf_sum += 1.0f;
            float4 t = s_lohi[bidx[a]];
            float wx = fmaxf(fminf(hi1x[a], t.z) - fmaxf(lo1x[a], t.x), 0.0f);
            float wy = fmaxf(fminf(hi1y[a], t.w) - fmaxf(lo1y[a], t.y), 0.0f);
            float inter = wx * wy;
            float uni = (a1[a] - 1e-6f) + s_area[bidx[a]] - inter;
            float iou = __fdividef(inter, uni + 1e-6f);
            float ex = fmaxf(fmaxf(hi1x[a], t.z) - fminf(lo1x[a], t.x), 0.0f);
            float ey = fmaxf(fmaxf(hi1y[a], t.w) - fminf(lo1y[a], t.y), 0.0f);
            float enc = ex * ey;
            bbox += 1.0f - (iou - __fdividef(enc - uni, enc + 1e-6f));
        }
    }

    // ── deterministic compaction of positives (order = anchor order) ──
    int c = 0;
    #pragma unroll
    for (int a = 0; a < APT; a++) c += pos[a] ? 1 : 0;
    int pre = c;
    #pragma unroll
    for (int o = 1; o < 32; o <<= 1) {
        int n = __shfl_up_sync(0xFFFFFFFFu, pre, o);
        if (lane >= o) pre += n;
    }
    if (lane == 31) s_wtot[wid] = pre;
    __syncthreads();
    int wbase = 0, P = 0;
    #pragma unroll
    for (int w = 0; w < NWARP; w++) {
        wbase += (w < wid) ? s_wtot[w] : 0;
        P += s_wtot[w];
    }
    int ofs = wbase + pre - c;  // exclusive prefix
    #pragma unroll
    for (int a = 0; a < APT; a++) {
        if (pos[a]) {
            s_pos_row[ofs] = base + a;
            s_pos_lab[ofs] = s_lab[bidx[a]];
            ofs++;
        }
    }
    __syncthreads();

    // ── focal loss over positives (P*80 items, cooperative) ──
    float fl = 0.0f;
    const int items = P * NCLS;
    for (int i = tid; i < items; i += THREADS) {
        int a = i / NCLS;
        int ccol = i - a * NCLS;
        float x = cls[s_pos_row[a] * NCLS + ccol];
        bool t = (ccol == s_pos_lab[a]);
        float e  = __expf(-fabsf(x));
        float sp = __logf(1.0f + e);
        float s  = __fdividef(1.0f, 1.0f + e);
        float p  = (x >= 0.0f) ? s : (1.0f - s);
        float one_m_pt = t ? (1.0f - p) : p;
        float ce = sp + fmaxf(t ? -x : x, 0.0f);
        float at = t ? 0.25f : 0.75f;
        fl += at * one_m_pt * one_m_pt * ce;
    }

    // ── block reduction of (bce, posf, bbox, fl) — deterministic ──
    float vals[4] = {bce, posf_sum, bbox, fl};
    #pragma unroll
    for (int k = 0; k < 4; k++) {
        float v = vals[k];
        #pragma unroll
        for (int o = 16; o > 0; o >>= 1) v += __shfl_down_sync(0xFFFFFFFFu, v, o);
        if (lane == 0) s_red[wid] = v;
        __syncthreads();
        if (tid == 0) {
            float r = 0.0f;
            #pragma unroll
            for (int w = 0; w < NWARP; w++) r += s_red[w];
            g_part[blockIdx.x * 4 + k] = r;
        }
        __syncthreads();
    }

    // ── last-block finalize ──
    __threadfence();
    if (tid == 0) s_is_last = (atomicAdd(&g_count, 1) == NBLOCKS - 1) ? 1u : 0u;
    __syncthreads();
    if (!s_is_last) return;
    __threadfence();

    {
        int fimg = tid >> 4;        // 0..7 (128 threads = 8 imgs x 16 slots)
        int sub  = tid & 15;        // 0..15
        float v0 = 0, v1 = 0, v2 = 0, v3 = 0;
        for (int s = sub; s < NBLK_PER_IMG; s += 16) {
            int b = fimg * NBLK_PER_IMG + s;
            v0 += g_part[b * 4 + 0];
            v1 += g_part[b * 4 + 1];
            v2 += g_part[b * 4 + 2];
            v3 += g_part[b * 4 + 3];
        }
        #pragma unroll
        for (int o = 8; o > 0; o >>= 1) {
            v0 += __shfl_down_sync(0xFFFFFFFFu, v0, o, 16);
            v1 += __shfl_down_sync(0xFFFFFFFFu, v1, o, 16);
            v2 += __shfl_down_sync(0xFFFFFFFFu, v2, o, 16);
            v3 += __shfl_down_sync(0xFFFFFFFFu, v3, o, 16);
        }
        if (sub == 0) {
            s_img[fimg][0] = v0; s_img[fimg][1] = v1;
            s_img[fimg][2] = v2; s_img[fimg][3] = v3;
        }
        __syncthreads();
        if (tid == 0) {
            float obj_sum = 0, bbox_sum = 0, cls_sum = 0, num_pos = 0;
            #pragma unroll
            for (int i = 0; i < NIMG; i++) {
                float bces = s_img[i][0];
                float pc   = s_img[i][1];
                float bb   = s_img[i][2];
                float fls  = s_img[i][3];
                obj_sum  += bces * (1.0f * pc + 0.5f * ((float)NANCH - pc));
                bbox_sum += bb;
                cls_sum  += fls / fmaxf(pc * (float)NCLS, 1.0f);
                num_pos  += pc;
            }
            num_pos = fmaxf(num_pos, 1.0f);
            out[0] = obj_sum / (float)NIMG
                   + 5.0f * bbox_sum / num_pos
                   + cls_sum / (float)NIMG;
            g_count = 0;   // reset for next graph replay
        }
    }
}

extern "C" void kernel_launch(void* const* d_in, const int* in_sizes, int n_in,
                              void* d_out, int out_size) {
    const float* obj   = (const float*)d_in[0];
    const float* boxes = (const float*)d_in[1];
    const float* cls   = (const float*)d_in[2];
    const float* tbox  = (const float*)d_in[3];
    const int*   tlab  = (const int*)d_in[4];
    float* out = (float*)d_out;

    loss_fused<<<NBLOCKS, THREADS>>>(obj, boxes, cls, tbox, tlab, out);
}